// round 12
// baseline (speedup 1.0000x reference)
#include <cuda_runtime.h>
#include <cuda_bf16.h>
#include <mma.h>

using namespace nvcuda;

// Problem constants
#define B_ 4
#define T_ 2048
#define C_ 1024
#define H_ 16
#define D_ 64
#define M_TOT 8192      // B*T
#define N3_ 3072        // 3*C

// Scratch: K/Q/V in [B,H,T,D] layout, fp32 (tf32-rounded values)
__device__ float g_K[B_ * H_ * T_ * D_];
__device__ float g_Q[B_ * H_ * T_ * D_];
__device__ float g_V[B_ * H_ * T_ * D_];

__device__ __forceinline__ float to_tf32(float x) {
    float r;
    asm("cvt.rna.tf32.f32 %0, %1;" : "=f"(r) : "f"(x));
    return r;
}

// ============================================================================
// Kernel 1: QKV projection GEMM  (qkv = x @ W + b), tf32 wmma
//   CTA tile 128(M) x 128(N), K-step 32. 256 threads = 8 warps (4x2).
//   Epilogue: +bias, tf32-round, scatter to g_K/g_Q/g_V in [B,H,T,D].
// SMEM layout (bytes):
//   As: [128][36] f32 @ 0       = 18432
//   Bs: [32][132] f32 @ 18432   = 16896
//   stage: 8 warps * 16*20 f32 @ 35328 = 10240   -> total 45568
// ============================================================================
#define GA_LD 36
#define GB_LD 132
#define GEMM_SMEM 45568

__global__ void __launch_bounds__(256) qkv_gemm(const float* __restrict__ x,
                                                const float* __restrict__ w,
                                                const float* __restrict__ bias) {
    extern __shared__ char smc[];
    float* As = (float*)smc;                 // [128][GA_LD]
    float* Bs = (float*)(smc + 18432);       // [32][GB_LD]
    float* stage = (float*)(smc + 35328);    // per-warp [16][20]

    const int tid = threadIdx.x;
    const int wid = tid >> 5;
    const int lane = tid & 31;
    const int warp_m = wid >> 1;   // 0..3
    const int warp_n = wid & 1;    // 0..1
    const int m0 = blockIdx.x * 128;
    const int n0 = blockIdx.y * 128;

    wmma::fragment<wmma::accumulator, 16, 16, 8, float> acc[2][4];
#pragma unroll
    for (int i = 0; i < 2; i++)
#pragma unroll
        for (int j = 0; j < 4; j++) wmma::fill_fragment(acc[i][j], 0.0f);

    for (int k0 = 0; k0 < 1024; k0 += 32) {
        // Load A tile 128x32 (fp32 -> tf32-rounded into smem)
#pragma unroll
        for (int it = 0; it < 4; it++) {
            int v = tid + it * 256;
            int r = v >> 3;
            int q = (v & 7) << 2;
            float4 f = *(const float4*)(x + (size_t)(m0 + r) * 1024 + k0 + q);
            float* d = As + r * GA_LD + q;
            d[0] = to_tf32(f.x); d[1] = to_tf32(f.y);
            d[2] = to_tf32(f.z); d[3] = to_tf32(f.w);
        }
        // Load B tile 32x128
#pragma unroll
        for (int it = 0; it < 4; it++) {
            int v = tid + it * 256;
            int r = v >> 5;
            int q = (v & 31) << 2;
            float4 f = *(const float4*)(w + (size_t)(k0 + r) * 3072 + n0 + q);
            float* d = Bs + r * GB_LD + q;
            d[0] = to_tf32(f.x); d[1] = to_tf32(f.y);
            d[2] = to_tf32(f.z); d[3] = to_tf32(f.w);
        }
        __syncthreads();

#pragma unroll
        for (int kk = 0; kk < 32; kk += 8) {
            wmma::fragment<wmma::matrix_a, 16, 16, 8, wmma::precision::tf32, wmma::row_major> af[2];
            wmma::load_matrix_sync(af[0], As + (warp_m * 32 +  0) * GA_LD + kk, GA_LD);
            wmma::load_matrix_sync(af[1], As + (warp_m * 32 + 16) * GA_LD + kk, GA_LD);
#pragma unroll
            for (int c = 0; c < 4; c++) {
                wmma::fragment<wmma::matrix_b, 16, 16, 8, wmma::precision::tf32, wmma::row_major> bf;
                wmma::load_matrix_sync(bf, Bs + kk * GB_LD + warp_n * 64 + c * 16, GB_LD);
                wmma::mma_sync(acc[0][c], af[0], bf, acc[0][c]);
                wmma::mma_sync(acc[1][c], af[1], bf, acc[1][c]);
            }
        }
        __syncthreads();
    }

    // Epilogue: stage each 16x16 fragment, add bias, scatter
    float* st = stage + wid * 16 * 20;
    const int rr = lane >> 1;
    const int cc = (lane & 1) << 3;
#pragma unroll
    for (int fi = 0; fi < 2; fi++) {
#pragma unroll
        for (int fj = 0; fj < 4; fj++) {
            wmma::store_matrix_sync(st, acc[fi][fj], 20, wmma::mem_row_major);
            __syncwarp();
            int r = m0 + warp_m * 32 + fi * 16 + rr;       // global row in [0, 8192)
            int n = n0 + warp_n * 64 + fj * 16 + cc;       // global col in [0, 3072)
            int sec = n >> 10;                             // 0=K, 1=Q, 2=V  (ref split order!)
            int c = n & 1023;
            int h = c >> 6;
            int d = c & 63;
            int bb = r >> 11;
            int t = r & 2047;
            float* base = (sec == 0) ? g_K : (sec == 1) ? g_Q : g_V;
            float* dst = base + ((size_t)((bb * H_ + h) * T_ + t)) * D_ + d;

            float4 bv0 = *(const float4*)(bias + n);
            float4 bv1 = *(const float4*)(bias + n + 4);
            const float* srow = st + rr * 20 + cc;
            float4 o0, o1;
            o0.x = to_tf32(srow[0] + bv0.x);
            o0.y = to_tf32(srow[1] + bv0.y);
            o0.z = to_tf32(srow[2] + bv0.z);
            o0.w = to_tf32(srow[3] + bv0.w);
            o1.x = to_tf32(srow[4] + bv1.x);
            o1.y = to_tf32(srow[5] + bv1.y);
            o1.z = to_tf32(srow[6] + bv1.z);
            o1.w = to_tf32(srow[7] + bv1.w);
            *(float4*)dst = o0;
            *(float4*)(dst + 4) = o1;
            __syncwarp();
        }
    }
}

// ============================================================================
// Kernel 2: causal flash attention, tf32 wmma
//   One CTA per (b, h, 64-row q tile). 256 threads = 8 warps (4x2 over 64x64).
//   Online softmax; S/P share a buffer; O accumulated in smem fp32.
// SMEM (bytes), ld=68 floats everywhere:
//   Qs @ 0, Ks @ 17408, Vs @ 34816, Ss @ 52224, Os @ 69632,
//   m @ 87040 (64 f32), l @ 87296 (64 f32)  -> total 87552
// ============================================================================
#define F_LD 68
#define FLASH_SMEM 87552

__global__ void __launch_bounds__(256) flash_attn(float* __restrict__ out) {
    extern __shared__ char smc[];
    float* Qs  = (float*)smc;
    float* Ks  = (float*)(smc + 17408);
    float* Vs  = (float*)(smc + 34816);
    float* Ss  = (float*)(smc + 52224);
    float* Os  = (float*)(smc + 69632);
    float* m_sm = (float*)(smc + 87040);
    float* l_sm = (float*)(smc + 87296);

    const int tid = threadIdx.x;
    const int wid = tid >> 5;
    const int warp_m = wid >> 1;   // 0..3 (16-row strip)
    const int warp_n = wid & 1;    // 0..1 (32-col strip)
    const int qt = blockIdx.x;     // 0..31
    const int h  = blockIdx.y;     // 0..15
    const int b  = blockIdx.z;     // 0..3
    const int bh = b * H_ + h;
    const float* Qg = g_Q + (size_t)bh * T_ * D_;
    const float* Kg = g_K + (size_t)bh * T_ * D_;
    const float* Vg = g_V + (size_t)bh * T_ * D_;
    const int q0 = qt * 64;

    // Load Q tile (already tf32-rounded by the GEMM epilogue)
#pragma unroll
    for (int it = 0; it < 4; it++) {
        int v = tid + it * 256;
        int r = v >> 4;
        int q = (v & 15) << 2;
        *(float4*)(Qs + r * F_LD + q) = *(const float4*)(Qg + (size_t)(q0 + r) * 64 + q);
    }
    const int row  = tid >> 2;  // 0..63
    const int part = tid & 3;   // 0..3 (16 cols each)
    // Init O, m, l
    {
        float4 z = make_float4(0.f, 0.f, 0.f, 0.f);
#pragma unroll
        for (int i = 0; i < 4; i++)
            *(float4*)(Os + row * F_LD + part * 16 + i * 4) = z;
        if (tid < 64) { m_sm[tid] = -1e30f; l_sm[tid] = 0.f; }
    }
    __syncthreads();

    for (int j = 0; j <= qt; j++) {
        const int k0 = j * 64;
        // Load K, V tiles
#pragma unroll
        for (int it = 0; it < 4; it++) {
            int v = tid + it * 256;
            int r = v >> 4;
            int q = (v & 15) << 2;
            *(float4*)(Ks + r * F_LD + q) = *(const float4*)(Kg + (size_t)(k0 + r) * 64 + q);
            *(float4*)(Vs + r * F_LD + q) = *(const float4*)(Vg + (size_t)(k0 + r) * 64 + q);
        }
        __syncthreads();

        // S = Q * K^T  (K row-major over d => col_major B operand)
        {
            wmma::fragment<wmma::accumulator, 16, 16, 8, float> sacc[2];
            wmma::fill_fragment(sacc[0], 0.f);
            wmma::fill_fragment(sacc[1], 0.f);
            const float* abase = Qs + warp_m * 16 * F_LD;
#pragma unroll
            for (int kk = 0; kk < 64; kk += 8) {
                wmma::fragment<wmma::matrix_a, 16, 16, 8, wmma::precision::tf32, wmma::row_major> af;
                wmma::load_matrix_sync(af, abase + kk, F_LD);
#pragma unroll
                for (int c = 0; c < 2; c++) {
                    wmma::fragment<wmma::matrix_b, 16, 16, 8, wmma::precision::tf32, wmma::col_major> bf;
                    wmma::load_matrix_sync(bf, Ks + (warp_n * 32 + c * 16) * F_LD + kk, F_LD);
                    wmma::mma_sync(sacc[c], af, bf, sacc[c]);
                }
            }
            wmma::store_matrix_sync(Ss + warp_m * 16 * F_LD + warp_n * 32,      sacc[0], F_LD, wmma::mem_row_major);
            wmma::store_matrix_sync(Ss + warp_m * 16 * F_LD + warp_n * 32 + 16, sacc[1], F_LD, wmma::mem_row_major);
        }
        __syncthreads();

        // Online softmax (4 threads per row, 16 cols each); P overwrites S.
        {
            const int qg = q0 + row;
            float s[16];
            float mx = -1e30f;
#pragma unroll
            for (int i = 0; i < 16; i++) {
                int c = part * 16 + i;
                float v = Ss[row * F_LD + c] * 0.125f;   // 1/sqrt(64)
                if (k0 + c > qg) v = -1e30f;             // causal mask
                s[i] = v;
                mx = fmaxf(mx, v);
            }
            mx = fmaxf(mx, __shfl_xor_sync(0xffffffffu, mx, 1));
            mx = fmaxf(mx, __shfl_xor_sync(0xffffffffu, mx, 2));
            float m_old = m_sm[row];
            float m_new = fmaxf(m_old, mx);
            float corr  = __expf(m_old - m_new);
            float psum = 0.f;
#pragma unroll
            for (int i = 0; i < 16; i++) {
                float p = __expf(s[i] - m_new);
                psum += p;
                Ss[row * F_LD + part * 16 + i] = to_tf32(p);
            }
            psum += __shfl_xor_sync(0xffffffffu, psum, 1);
            psum += __shfl_xor_sync(0xffffffffu, psum, 2);
            // Rescale O rows
#pragma unroll
            for (int i = 0; i < 16; i++)
                Os[row * F_LD + part * 16 + i] *= corr;
            __syncwarp();
            if (part == 0) {
                m_sm[row] = m_new;
                l_sm[row] = l_sm[row] * corr + psum;
            }
        }
        __syncthreads();

        // O += P * V
        {
            float* obase = Os + warp_m * 16 * F_LD + warp_n * 32;
            wmma::fragment<wmma::accumulator, 16, 16, 8, float> oacc[2];
            wmma::load_matrix_sync(oacc[0], obase,      F_LD, wmma::mem_row_major);
            wmma::load_matrix_sync(oacc[1], obase + 16, F_LD, wmma::mem_row_major);
#pragma unroll
            for (int kk = 0; kk < 64; kk += 8) {
                wmma::fragment<wmma::matrix_a, 16, 16, 8, wmma::precision::tf32, wmma::row_major> af;
                wmma::load_matrix_sync(af, Ss + warp_m * 16 * F_LD + kk, F_LD);
#pragma unroll
                for (int c = 0; c < 2; c++) {
                    wmma::fragment<wmma::matrix_b, 16, 16, 8, wmma::precision::tf32, wmma::row_major> bf;
                    wmma::load_matrix_sync(bf, Vs + kk * F_LD + warp_n * 32 + c * 16, F_LD);
                    wmma::mma_sync(oacc[c], af, bf, oacc[c]);
                }
            }
            wmma::store_matrix_sync(obase,      oacc[0], F_LD, wmma::mem_row_major);
            wmma::store_matrix_sync(obase + 16, oacc[1], F_LD, wmma::mem_row_major);
        }
        __syncthreads();
    }

    // Final normalize + write: y[b, q, h*64 + d]
    {
        float inv = 1.0f / l_sm[row];
        const float* src = Os + row * F_LD + part * 16;
        float* dst = out + ((size_t)(b * T_ + q0 + row)) * C_ + h * 64 + part * 16;
#pragma unroll
        for (int i = 0; i < 4; i++) {
            float4 v = *(const float4*)(src + i * 4);
            v.x *= inv; v.y *= inv; v.z *= inv; v.w *= inv;
            *(float4*)(dst + i * 4) = v;
        }
    }
}

// ============================================================================
// Launch
// ============================================================================
extern "C" void kernel_launch(void* const* d_in, const int* in_sizes, int n_in,
                              void* d_out, int out_size) {
    (void)in_sizes; (void)n_in; (void)out_size;
    const float* x    = (const float*)d_in[0];   // [B, T, C]
    const float* wqkv = (const float*)d_in[1];   // [C, 3C]
    const float* bqkv = (const float*)d_in[2];   // [3C]
    float* out = (float*)d_out;                  // [B, T, C]

    cudaFuncSetAttribute(flash_attn, cudaFuncAttributeMaxDynamicSharedMemorySize, FLASH_SMEM);

    qkv_gemm<<<dim3(64, 24), 256, GEMM_SMEM>>>(x, wqkv, bqkv);
    flash_attn<<<dim3(32, 16, 4), 256, FLASH_SMEM>>>(out);
}

// round 13
// speedup vs baseline: 1.0108x; 1.0108x over previous
#include <cuda_runtime.h>
#include <cuda_bf16.h>
#include <mma.h>

using namespace nvcuda;

// Problem constants
#define B_ 4
#define T_ 2048
#define C_ 1024
#define H_ 16
#define D_ 64
#define M_TOT 8192      // B*T
#define N3_ 3072        // 3*C

// Scratch: K/Q/V in [B,H,T,D] layout, fp32 (tf32-rounded values)
__device__ float g_K[B_ * H_ * T_ * D_];
__device__ float g_Q[B_ * H_ * T_ * D_];
__device__ float g_V[B_ * H_ * T_ * D_];

__device__ __forceinline__ float to_tf32(float x) {
    float r;
    asm("cvt.rna.tf32.f32 %0, %1;" : "=f"(r) : "f"(x));
    return r;
}

// ============================================================================
// Kernel 1: QKV projection GEMM  (qkv = x @ W + b), tf32 wmma
//   CTA tile 128(M) x 128(N), K-step 32. 256 threads = 8 warps (4x2).
//   Epilogue: +bias, tf32-round, scatter to g_K/g_Q/g_V in [B,H,T,D].
// SMEM layout (bytes):
//   As: [128][36] f32 @ 0       = 18432
//   Bs: [32][132] f32 @ 18432   = 16896
//   stage: 8 warps * 16*20 f32 @ 35328 = 10240   -> total 45568
// ============================================================================
#define GA_LD 36
#define GB_LD 132
#define GEMM_SMEM 45568

__global__ void __launch_bounds__(256) qkv_gemm(const float* __restrict__ x,
                                                const float* __restrict__ w,
                                                const float* __restrict__ bias) {
    extern __shared__ char smc[];
    float* As = (float*)smc;                 // [128][GA_LD]
    float* Bs = (float*)(smc + 18432);       // [32][GB_LD]
    float* stage = (float*)(smc + 35328);    // per-warp [16][20]

    const int tid = threadIdx.x;
    const int wid = tid >> 5;
    const int lane = tid & 31;
    const int warp_m = wid >> 1;   // 0..3
    const int warp_n = wid & 1;    // 0..1
    const int m0 = blockIdx.x * 128;
    const int n0 = blockIdx.y * 128;

    wmma::fragment<wmma::accumulator, 16, 16, 8, float> acc[2][4];
#pragma unroll
    for (int i = 0; i < 2; i++)
#pragma unroll
        for (int j = 0; j < 4; j++) wmma::fill_fragment(acc[i][j], 0.0f);

    for (int k0 = 0; k0 < 1024; k0 += 32) {
        // Load A tile 128x32 (fp32 -> tf32-rounded into smem)
#pragma unroll
        for (int it = 0; it < 4; it++) {
            int v = tid + it * 256;
            int r = v >> 3;
            int q = (v & 7) << 2;
            float4 f = *(const float4*)(x + (size_t)(m0 + r) * 1024 + k0 + q);
            float* d = As + r * GA_LD + q;
            d[0] = to_tf32(f.x); d[1] = to_tf32(f.y);
            d[2] = to_tf32(f.z); d[3] = to_tf32(f.w);
        }
        // Load B tile 32x128
#pragma unroll
        for (int it = 0; it < 4; it++) {
            int v = tid + it * 256;
            int r = v >> 5;
            int q = (v & 31) << 2;
            float4 f = *(const float4*)(w + (size_t)(k0 + r) * 3072 + n0 + q);
            float* d = Bs + r * GB_LD + q;
            d[0] = to_tf32(f.x); d[1] = to_tf32(f.y);
            d[2] = to_tf32(f.z); d[3] = to_tf32(f.w);
        }
        __syncthreads();

#pragma unroll
        for (int kk = 0; kk < 32; kk += 8) {
            wmma::fragment<wmma::matrix_a, 16, 16, 8, wmma::precision::tf32, wmma::row_major> af[2];
            wmma::load_matrix_sync(af[0], As + (warp_m * 32 +  0) * GA_LD + kk, GA_LD);
            wmma::load_matrix_sync(af[1], As + (warp_m * 32 + 16) * GA_LD + kk, GA_LD);
#pragma unroll
            for (int c = 0; c < 4; c++) {
                wmma::fragment<wmma::matrix_b, 16, 16, 8, wmma::precision::tf32, wmma::row_major> bf;
                wmma::load_matrix_sync(bf, Bs + kk * GB_LD + warp_n * 64 + c * 16, GB_LD);
                wmma::mma_sync(acc[0][c], af[0], bf, acc[0][c]);
                wmma::mma_sync(acc[1][c], af[1], bf, acc[1][c]);
            }
        }
        __syncthreads();
    }

    // Epilogue: stage each 16x16 fragment, add bias, scatter
    float* st = stage + wid * 16 * 20;
    const int rr = lane >> 1;
    const int cc = (lane & 1) << 3;
#pragma unroll
    for (int fi = 0; fi < 2; fi++) {
#pragma unroll
        for (int fj = 0; fj < 4; fj++) {
            wmma::store_matrix_sync(st, acc[fi][fj], 20, wmma::mem_row_major);
            __syncwarp();
            int r = m0 + warp_m * 32 + fi * 16 + rr;       // global row in [0, 8192)
            int n = n0 + warp_n * 64 + fj * 16 + cc;       // global col in [0, 3072)
            int sec = n >> 10;                             // 0=K, 1=Q, 2=V  (ref split order!)
            int c = n & 1023;
            int h = c >> 6;
            int d = c & 63;
            int bb = r >> 11;
            int t = r & 2047;
            float* base = (sec == 0) ? g_K : (sec == 1) ? g_Q : g_V;
            float* dst = base + ((size_t)((bb * H_ + h) * T_ + t)) * D_ + d;

            float4 bv0 = *(const float4*)(bias + n);
            float4 bv1 = *(const float4*)(bias + n + 4);
            const float* srow = st + rr * 20 + cc;
            float4 o0, o1;
            o0.x = to_tf32(srow[0] + bv0.x);
            o0.y = to_tf32(srow[1] + bv0.y);
            o0.z = to_tf32(srow[2] + bv0.z);
            o0.w = to_tf32(srow[3] + bv0.w);
            o1.x = to_tf32(srow[4] + bv1.x);
            o1.y = to_tf32(srow[5] + bv1.y);
            o1.z = to_tf32(srow[6] + bv1.z);
            o1.w = to_tf32(srow[7] + bv1.w);
            *(float4*)dst = o0;
            *(float4*)(dst + 4) = o1;
            __syncwarp();
        }
    }
}

// ============================================================================
// Kernel 2: causal flash attention, tf32 wmma
//   One CTA per (b, h, 64-row q tile). 256 threads = 8 warps (4x2 over 64x64).
//   Online softmax; S/P share a buffer; O accumulated in smem fp32.
// SMEM (bytes), ld=68 floats everywhere:
//   Qs @ 0, Ks @ 17408, Vs @ 34816, Ss @ 52224, Os @ 69632,
//   m @ 87040 (64 f32), l @ 87296 (64 f32)  -> total 87552
// ============================================================================
#define F_LD 68
#define FLASH_SMEM 87552

__global__ void __launch_bounds__(256) flash_attn(float* __restrict__ out) {
    extern __shared__ char smc[];
    float* Qs  = (float*)smc;
    float* Ks  = (float*)(smc + 17408);
    float* Vs  = (float*)(smc + 34816);
    float* Ss  = (float*)(smc + 52224);
    float* Os  = (float*)(smc + 69632);
    float* m_sm = (float*)(smc + 87040);
    float* l_sm = (float*)(smc + 87296);

    const int tid = threadIdx.x;
    const int wid = tid >> 5;
    const int warp_m = wid >> 1;   // 0..3 (16-row strip)
    const int warp_n = wid & 1;    // 0..1 (32-col strip)
    const int qt = blockIdx.x;     // 0..31
    const int h  = blockIdx.y;     // 0..15
    const int b  = blockIdx.z;     // 0..3
    const int bh = b * H_ + h;
    const float* Qg = g_Q + (size_t)bh * T_ * D_;
    const float* Kg = g_K + (size_t)bh * T_ * D_;
    const float* Vg = g_V + (size_t)bh * T_ * D_;
    const int q0 = qt * 64;

    // Load Q tile (already tf32-rounded by the GEMM epilogue)
#pragma unroll
    for (int it = 0; it < 4; it++) {
        int v = tid + it * 256;
        int r = v >> 4;
        int q = (v & 15) << 2;
        *(float4*)(Qs + r * F_LD + q) = *(const float4*)(Qg + (size_t)(q0 + r) * 64 + q);
    }
    const int row  = tid >> 2;  // 0..63
    const int part = tid & 3;   // 0..3 (16 cols each)
    // Init O, m, l
    {
        float4 z = make_float4(0.f, 0.f, 0.f, 0.f);
#pragma unroll
        for (int i = 0; i < 4; i++)
            *(float4*)(Os + row * F_LD + part * 16 + i * 4) = z;
        if (tid < 64) { m_sm[tid] = -1e30f; l_sm[tid] = 0.f; }
    }
    __syncthreads();

    for (int j = 0; j <= qt; j++) {
        const int k0 = j * 64;
        // Load K, V tiles
#pragma unroll
        for (int it = 0; it < 4; it++) {
            int v = tid + it * 256;
            int r = v >> 4;
            int q = (v & 15) << 2;
            *(float4*)(Ks + r * F_LD + q) = *(const float4*)(Kg + (size_t)(k0 + r) * 64 + q);
            *(float4*)(Vs + r * F_LD + q) = *(const float4*)(Vg + (size_t)(k0 + r) * 64 + q);
        }
        __syncthreads();

        // S = Q * K^T  (K row-major over d => col_major B operand)
        {
            wmma::fragment<wmma::accumulator, 16, 16, 8, float> sacc[2];
            wmma::fill_fragment(sacc[0], 0.f);
            wmma::fill_fragment(sacc[1], 0.f);
            const float* abase = Qs + warp_m * 16 * F_LD;
#pragma unroll
            for (int kk = 0; kk < 64; kk += 8) {
                wmma::fragment<wmma::matrix_a, 16, 16, 8, wmma::precision::tf32, wmma::row_major> af;
                wmma::load_matrix_sync(af, abase + kk, F_LD);
#pragma unroll
                for (int c = 0; c < 2; c++) {
                    wmma::fragment<wmma::matrix_b, 16, 16, 8, wmma::precision::tf32, wmma::col_major> bf;
                    wmma::load_matrix_sync(bf, Ks + (warp_n * 32 + c * 16) * F_LD + kk, F_LD);
                    wmma::mma_sync(sacc[c], af, bf, sacc[c]);
                }
            }
            wmma::store_matrix_sync(Ss + warp_m * 16 * F_LD + warp_n * 32,      sacc[0], F_LD, wmma::mem_row_major);
            wmma::store_matrix_sync(Ss + warp_m * 16 * F_LD + warp_n * 32 + 16, sacc[1], F_LD, wmma::mem_row_major);
        }
        __syncthreads();

        // Online softmax (4 threads per row, 16 cols each); P overwrites S.
        {
            const int qg = q0 + row;
            float s[16];
            float mx = -1e30f;
#pragma unroll
            for (int i = 0; i < 16; i++) {
                int c = part * 16 + i;
                float v = Ss[row * F_LD + c] * 0.125f;   // 1/sqrt(64)
                if (k0 + c > qg) v = -1e30f;             // causal mask
                s[i] = v;
                mx = fmaxf(mx, v);
            }
            mx = fmaxf(mx, __shfl_xor_sync(0xffffffffu, mx, 1));
            mx = fmaxf(mx, __shfl_xor_sync(0xffffffffu, mx, 2));
            float m_old = m_sm[row];
            float m_new = fmaxf(m_old, mx);
            float corr  = __expf(m_old - m_new);
            float psum = 0.f;
#pragma unroll
            for (int i = 0; i < 16; i++) {
                float p = __expf(s[i] - m_new);
                psum += p;
                Ss[row * F_LD + part * 16 + i] = to_tf32(p);
            }
            psum += __shfl_xor_sync(0xffffffffu, psum, 1);
            psum += __shfl_xor_sync(0xffffffffu, psum, 2);
            // Rescale O rows
#pragma unroll
            for (int i = 0; i < 16; i++)
                Os[row * F_LD + part * 16 + i] *= corr;
            __syncwarp();
            if (part == 0) {
                m_sm[row] = m_new;
                l_sm[row] = l_sm[row] * corr + psum;
            }
        }
        __syncthreads();

        // O += P * V
        {
            float* obase = Os + warp_m * 16 * F_LD + warp_n * 32;
            wmma::fragment<wmma::accumulator, 16, 16, 8, float> oacc[2];
            wmma::load_matrix_sync(oacc[0], obase,      F_LD, wmma::mem_row_major);
            wmma::load_matrix_sync(oacc[1], obase + 16, F_LD, wmma::mem_row_major);
#pragma unroll
            for (int kk = 0; kk < 64; kk += 8) {
                wmma::fragment<wmma::matrix_a, 16, 16, 8, wmma::precision::tf32, wmma::row_major> af;
                wmma::load_matrix_sync(af, Ss + warp_m * 16 * F_LD + kk, F_LD);
#pragma unroll
                for (int c = 0; c < 2; c++) {
                    wmma::fragment<wmma::matrix_b, 16, 16, 8, wmma::precision::tf32, wmma::row_major> bf;
                    wmma::load_matrix_sync(bf, Vs + kk * F_LD + warp_n * 32 + c * 16, F_LD);
                    wmma::mma_sync(oacc[c], af, bf, oacc[c]);
                }
            }
            wmma::store_matrix_sync(obase,      oacc[0], F_LD, wmma::mem_row_major);
            wmma::store_matrix_sync(obase + 16, oacc[1], F_LD, wmma::mem_row_major);
        }
        __syncthreads();
    }

    // Final normalize + write: y[b, q, h*64 + d]
    {
        float inv = 1.0f / l_sm[row];
        const float* src = Os + row * F_LD + part * 16;
        float* dst = out + ((size_t)(b * T_ + q0 + row)) * C_ + h * 64 + part * 16;
#pragma unroll
        for (int i = 0; i < 4; i++) {
            float4 v = *(const float4*)(src + i * 4);
            v.x *= inv; v.y *= inv; v.z *= inv; v.w *= inv;
            *(float4*)(dst + i * 4) = v;
        }
    }
}

// ============================================================================
// Launch
// ============================================================================
extern "C" void kernel_launch(void* const* d_in, const int* in_sizes, int n_in,
                              void* d_out, int out_size) {
    (void)in_sizes; (void)n_in; (void)out_size;
    const float* x    = (const float*)d_in[0];   // [B, T, C]
    const float* wqkv = (const float*)d_in[1];   // [C, 3C]
    const float* bqkv = (const float*)d_in[2];   // [3C]
    float* out = (float*)d_out;                  // [B, T, C]

    cudaFuncSetAttribute(flash_attn, cudaFuncAttributeMaxDynamicSharedMemorySize, FLASH_SMEM);

    qkv_gemm<<<dim3(64, 24), 256, GEMM_SMEM>>>(x, wqkv, bqkv);
    flash_attn<<<dim3(32, 16, 4), 256, FLASH_SMEM>>>(out);
}